// round 1
// baseline (speedup 1.0000x reference)
#include <cuda_runtime.h>
#include <cstdint>

// Problem constants (fixed by the reference)
#define BATCH 2
#define SEQ   2048
#define NHEAD 12
#define HSZ   64
#define HID   768          // NHEAD*HSZ
#define M_TOK (BATCH*SEQ)  // 4096
#define QKV_N (3*HID)      // 2304

// Scratch (allocation-free rule: __device__ globals)
__device__ float g_qkv[M_TOK * QKV_N];   // [4096, 2304]
__device__ float g_ctx[M_TOK * HID];     // [4096, 768]

// ---------------------------------------------------------------------------
// SGEMM: C[M,N] = A[M,K] @ B[K,N] + bias[N]
// 128x128 block tile, BK=8, 8x8 per-thread microtile, 256 threads.
// M % 128 == 0, N % 128 == 0, K % 8 == 0 (all hold here).
// ---------------------------------------------------------------------------
__global__ __launch_bounds__(256, 2)
void sgemm_bias_kernel(const float* __restrict__ A, const float* __restrict__ B,
                       const float* __restrict__ bias, float* __restrict__ C,
                       int M, int N, int K) {
    __shared__ float As[8][128];   // As[k][m] (A transposed in smem)
    __shared__ float Bs[8][128];   // Bs[k][n]

    const int tid = threadIdx.x;
    const int tx = tid & 15;       // 0..15 -> n
    const int ty = tid >> 4;       // 0..15 -> m
    const int bm = blockIdx.y * 128;
    const int bn = blockIdx.x * 128;

    // load mapping
    const int arow = tid >> 1;            // 0..127
    const int acol = (tid & 1) << 2;      // 0 or 4
    const int brow = tid >> 5;            // 0..7
    const int bcol = (tid & 31) << 2;     // 0..124

    float acc[8][8];
#pragma unroll
    for (int i = 0; i < 8; ++i)
#pragma unroll
        for (int j = 0; j < 8; ++j) acc[i][j] = 0.f;

    const float* Aptr = A + (size_t)(bm + arow) * K + acol;
    const float* Bptr = B + (size_t)brow * N + bn + bcol;

    for (int k0 = 0; k0 < K; k0 += 8) {
        float4 av = *(const float4*)(Aptr + k0);
        As[acol + 0][arow] = av.x;
        As[acol + 1][arow] = av.y;
        As[acol + 2][arow] = av.z;
        As[acol + 3][arow] = av.w;
        *(float4*)(&Bs[brow][bcol]) = *(const float4*)(Bptr + (size_t)k0 * N);
        __syncthreads();

#pragma unroll
        for (int kk = 0; kk < 8; ++kk) {
            float ra[8], rb[8];
            *(float4*)&ra[0] = *(const float4*)&As[kk][ty * 8];
            *(float4*)&ra[4] = *(const float4*)&As[kk][ty * 8 + 4];
            *(float4*)&rb[0] = *(const float4*)&Bs[kk][tx * 8];
            *(float4*)&rb[4] = *(const float4*)&Bs[kk][tx * 8 + 4];
#pragma unroll
            for (int i = 0; i < 8; ++i)
#pragma unroll
                for (int j = 0; j < 8; ++j)
                    acc[i][j] += ra[i] * rb[j];
        }
        __syncthreads();
    }

    // epilogue: + bias, vectorized store
#pragma unroll
    for (int i = 0; i < 8; ++i) {
        const int row = bm + ty * 8 + i;
        float* crow = C + (size_t)row * N;
#pragma unroll
        for (int j = 0; j < 8; j += 4) {
            const int col = bn + tx * 8 + j;
            float4 bv = *(const float4*)(bias + col);
            float4 ov;
            ov.x = acc[i][j + 0] + bv.x;
            ov.y = acc[i][j + 1] + bv.y;
            ov.z = acc[i][j + 2] + bv.z;
            ov.w = acc[i][j + 3] + bv.w;
            *(float4*)(crow + col) = ov;
        }
    }
}

// ---------------------------------------------------------------------------
// Fused causal attention (flash style), fp32.
// Block = (qt, h, b): 64 query rows, loops over 64-wide KV tiles 0..qt.
// 256 threads, 4x4 microtiles; all smem operands laid out so inner loops are
// float4 LDS + FFMA.
// ---------------------------------------------------------------------------
#define APAD 68
#define ATTN_SMEM (4 * 64 * APAD * 4)   // Qst, Kst, Vs, Pst

__global__ __launch_bounds__(256)
void attn_kernel(const float* __restrict__ qkv, float* __restrict__ ctx) {
    const int qt = blockIdx.x;   // query tile 0..31
    const int h  = blockIdx.y;   // head
    const int b  = blockIdx.z;   // batch

    const int tid = threadIdx.x;
    const int tx = tid & 15;     // -> kv col (S gemm) / d col (PV gemm, output)
    const int ty = tid >> 4;     // -> q row

    extern __shared__ float sm[];
    float* Qst = sm;                    // [d][q]  64 x APAD
    float* Kst = sm + 64 * APAD;        // [d][kv] 64 x APAD
    float* Vs  = sm + 2 * 64 * APAD;    // [kv][d] 64 x APAD
    float* Pst = sm + 3 * 64 * APAD;    // [kv][q] 64 x APAD

    const float scale = 0.125f;  // 1/sqrt(64)

    // ---- load Q tile transposed: Qst[d][q] ----
    const float* qbase = qkv + (size_t)(b * SEQ + qt * 64) * QKV_N + h * HSZ;
#pragma unroll
    for (int r = 0; r < 4; ++r) {
        const int f = tid + 256 * r;
        const int row = f >> 4;          // q row 0..63
        const int d4 = (f & 15) << 2;    // d 0..60
        float4 v = *(const float4*)(qbase + (size_t)row * QKV_N + d4);
        Qst[(d4 + 0) * APAD + row] = v.x;
        Qst[(d4 + 1) * APAD + row] = v.y;
        Qst[(d4 + 2) * APAD + row] = v.z;
        Qst[(d4 + 3) * APAD + row] = v.w;
    }

    float m[4], l[4], o[4][4];
#pragma unroll
    for (int i = 0; i < 4; ++i) {
        m[i] = -1e30f; l[i] = 0.f;
#pragma unroll
        for (int j = 0; j < 4; ++j) o[i][j] = 0.f;
    }

    for (int kt = 0; kt <= qt; ++kt) {
        // ---- load K tile transposed + V tile ----
        const float* kbase = qkv + (size_t)(b * SEQ + kt * 64) * QKV_N + HID + h * HSZ;
        const float* vbase = kbase + HID;
#pragma unroll
        for (int r = 0; r < 4; ++r) {
            const int f = tid + 256 * r;
            const int row = f >> 4;
            const int d4 = (f & 15) << 2;
            float4 kv4 = *(const float4*)(kbase + (size_t)row * QKV_N + d4);
            Kst[(d4 + 0) * APAD + row] = kv4.x;
            Kst[(d4 + 1) * APAD + row] = kv4.y;
            Kst[(d4 + 2) * APAD + row] = kv4.z;
            Kst[(d4 + 3) * APAD + row] = kv4.w;
            float4 vv = *(const float4*)(vbase + (size_t)row * QKV_N + d4);
            *(float4*)&Vs[row * APAD + d4] = vv;
        }
        __syncthreads();

        // ---- S = Q @ K^T (4x4 per thread) ----
        float s[4][4];
#pragma unroll
        for (int i = 0; i < 4; ++i)
#pragma unroll
            for (int j = 0; j < 4; ++j) s[i][j] = 0.f;

#pragma unroll 16
        for (int kk = 0; kk < 64; ++kk) {
            float rq[4], rk[4];
            *(float4*)rq = *(const float4*)&Qst[kk * APAD + ty * 4];
            *(float4*)rk = *(const float4*)&Kst[kk * APAD + tx * 4];
#pragma unroll
            for (int i = 0; i < 4; ++i)
#pragma unroll
                for (int j = 0; j < 4; ++j)
                    s[i][j] += rq[i] * rk[j];
        }

        // ---- scale + causal mask (only diagonal tile needs masking) ----
        if (kt == qt) {
#pragma unroll
            for (int i = 0; i < 4; ++i)
#pragma unroll
                for (int j = 0; j < 4; ++j) {
                    const int qi = ty * 4 + i, kj = tx * 4 + j;
                    s[i][j] = (kj > qi) ? -1e30f : s[i][j] * scale;
                }
        } else {
#pragma unroll
            for (int i = 0; i < 4; ++i)
#pragma unroll
                for (int j = 0; j < 4; ++j) s[i][j] *= scale;
        }

        // ---- online softmax (row groups = 16 lanes sharing ty) ----
#pragma unroll
        for (int i = 0; i < 4; ++i) {
            float rm = fmaxf(fmaxf(s[i][0], s[i][1]), fmaxf(s[i][2], s[i][3]));
#pragma unroll
            for (int off = 8; off > 0; off >>= 1)
                rm = fmaxf(rm, __shfl_xor_sync(0xffffffffu, rm, off));
            const float mn = fmaxf(m[i], rm);
            const float alpha = __expf(m[i] - mn);
            m[i] = mn;
            float rs = 0.f;
#pragma unroll
            for (int j = 0; j < 4; ++j) {
                s[i][j] = __expf(s[i][j] - mn);
                rs += s[i][j];
            }
#pragma unroll
            for (int off = 8; off > 0; off >>= 1)
                rs += __shfl_xor_sync(0xffffffffu, rs, off);
            l[i] = l[i] * alpha + rs;
#pragma unroll
            for (int j = 0; j < 4; ++j) o[i][j] *= alpha;
        }

        // ---- stage P transposed: Pst[kv][q] ----
#pragma unroll
        for (int i = 0; i < 4; ++i)
#pragma unroll
            for (int j = 0; j < 4; ++j)
                Pst[(tx * 4 + j) * APAD + ty * 4 + i] = s[i][j];
        __syncthreads();

        // ---- O += P @ V (rows=q via ty, cols=d via tx) ----
#pragma unroll 16
        for (int kk = 0; kk < 64; ++kk) {
            float rp[4], rv[4];
            *(float4*)rp = *(const float4*)&Pst[kk * APAD + ty * 4];
            *(float4*)rv = *(const float4*)&Vs[kk * APAD + tx * 4];
#pragma unroll
            for (int i = 0; i < 4; ++i)
#pragma unroll
                for (int j = 0; j < 4; ++j)
                    o[i][j] += rp[i] * rv[j];
        }
        __syncthreads();
    }

    // ---- normalize + write ctx [B,S,H] layout ----
    float* obase = ctx + (size_t)(b * SEQ + qt * 64) * HID + h * HSZ;
#pragma unroll
    for (int i = 0; i < 4; ++i) {
        const float invl = 1.0f / l[i];
        float4 w;
        w.x = o[i][0] * invl;
        w.y = o[i][1] * invl;
        w.z = o[i][2] * invl;
        w.w = o[i][3] * invl;
        *(float4*)(obase + (size_t)(ty * 4 + i) * HID + tx * 4) = w;
    }
}

// ---------------------------------------------------------------------------
extern "C" void kernel_launch(void* const* d_in, const int* in_sizes, int n_in,
                              void* d_out, int out_size) {
    const float* hs = (const float*)d_in[0];   // [2,2048,768]
    const float* w1 = (const float*)d_in[1];   // [768,2304]
    const float* b1 = (const float*)d_in[2];   // [2304]
    const float* w2 = (const float*)d_in[3];   // [768,768]
    const float* b2 = (const float*)d_in[4];   // [768]
    float* out = (float*)d_out;                // [2,2048,768]

    float* qkv;  cudaGetSymbolAddress((void**)&qkv, g_qkv);
    float* ctx;  cudaGetSymbolAddress((void**)&ctx, g_ctx);

    cudaFuncSetAttribute(attn_kernel,
                         cudaFuncAttributeMaxDynamicSharedMemorySize, ATTN_SMEM);

    // 1) QKV projection: [4096,768] @ [768,2304] + bias
    sgemm_bias_kernel<<<dim3(QKV_N / 128, M_TOK / 128), 256>>>(
        hs, w1, b1, qkv, M_TOK, QKV_N, HID);

    // 2) fused causal attention
    attn_kernel<<<dim3(SEQ / 64, NHEAD, BATCH), 256, ATTN_SMEM>>>(qkv, ctx);

    // 3) output projection: [4096,768] @ [768,768] + bias
    sgemm_bias_kernel<<<dim3(HID / 128, M_TOK / 128), 256>>>(
        ctx, w2, b2, out, M_TOK, HID, HID);
}

// round 3
// speedup vs baseline: 2.2695x; 2.2695x over previous
#include <cuda_runtime.h>
#include <cstdint>

// Problem constants (fixed by the reference)
#define BATCH 2
#define SEQ   2048
#define NHEAD 12
#define HSZ   64
#define HID   768
#define M_TOK (BATCH*SEQ)   // 4096
#define QKV_N (3*HID)       // 2304

// Scratch (allocation-free rule: __device__ globals)
__device__ float g_qkv[M_TOK * QKV_N];
__device__ float g_ctx[M_TOK * HID];

// ===========================================================================
// helpers: tf32 convert (round-to-nearest!) + mma.sync m16n8k8 tf32
// ===========================================================================
__device__ __forceinline__ float to_tf32(float x) {
    uint32_t u;
    asm("cvt.rna.tf32.f32 %0, %1;" : "=r"(u) : "f"(x));
    return __uint_as_float(u);
}
__device__ __forceinline__ float4 cvt4(float4 v) {
    float4 r;
    r.x = to_tf32(v.x); r.y = to_tf32(v.y);
    r.z = to_tf32(v.z); r.w = to_tf32(v.w);
    return r;
}
__device__ __forceinline__ void mma_tf32(float* d, const float* a, const float* b) {
    asm volatile(
        "mma.sync.aligned.m16n8k8.row.col.f32.tf32.tf32.f32 "
        "{%0,%1,%2,%3}, {%4,%5,%6,%7}, {%8,%9}, {%0,%1,%2,%3};"
        : "+f"(d[0]), "+f"(d[1]), "+f"(d[2]), "+f"(d[3])
        : "r"(__float_as_uint(a[0])), "r"(__float_as_uint(a[1])),
          "r"(__float_as_uint(a[2])), "r"(__float_as_uint(a[3])),
          "r"(__float_as_uint(b[0])), "r"(__float_as_uint(b[1])));
}

// ===========================================================================
// GEMM (tensor core, tf32): C[M,N] = A[M,K] @ B[K,N] + bias[N]
// 128x128 tile, BK=16, 256 threads (8 warps as 2x4), warp tile 64x32.
// As[m][28] (pad 28: bank = (28g+q)%32 distinct), Bs[k][136] (bank 8q+g).
// ===========================================================================
#define AS_STRIDE 3584   // 128*28
#define BS_STRIDE 2176   // 16*136
#define GEMM_SMEM ((2*AS_STRIDE + 2*BS_STRIDE)*4)

__global__ void __launch_bounds__(256, 2)
gemm_tc(const float* __restrict__ A, const float* __restrict__ B,
        const float* __restrict__ bias, float* __restrict__ C,
        int M, int N, int K) {
    extern __shared__ float sm[];
    float* AsBuf[2] = { sm, sm + AS_STRIDE };
    float* BsBuf[2] = { sm + 2 * AS_STRIDE, sm + 2 * AS_STRIDE + BS_STRIDE };

    const int tid = threadIdx.x;
    const int lane = tid & 31;
    const int wid = tid >> 5;
    const int g = lane >> 2;     // groupID
    const int q = lane & 3;      // threadID_in_group
    const int wm = wid >> 2;     // 0..1  (64 rows)
    const int wn = wid & 3;      // 0..3  (32 cols)
    const int bm = blockIdx.y * 128;
    const int bn = blockIdx.x * 128;

    // ---- staging maps ----
    const int arow = tid >> 1;
    const int ak0  = (tid & 1) * 8;
    const float* Ap = A + (size_t)(bm + arow) * K + ak0;

    const int br0 = tid >> 5,        bc0 = (tid & 31) * 4;
    const int br1 = (tid + 256) >> 5, bc1 = (tid & 31) * 4;
    const float* Bp0 = B + (size_t)br0 * N + bn + bc0;
    const float* Bp1 = B + (size_t)br1 * N + bn + bc1;

    float acc[4][4][4];
#pragma unroll
    for (int mf = 0; mf < 4; ++mf)
#pragma unroll
        for (int nf = 0; nf < 4; ++nf)
#pragma unroll
            for (int e = 0; e < 4; ++e) acc[mf][nf][e] = 0.f;

    const int nst = K / 16;   // 48

    // prologue: load stage 0
    float4 ra0 = *(const float4*)(Ap);
    float4 ra1 = *(const float4*)(Ap + 4);
    float4 rb0 = *(const float4*)(Bp0);
    float4 rb1 = *(const float4*)(Bp1);
    {
        float* a = AsBuf[0];
        *(float4*)&a[arow * 28 + ak0]     = cvt4(ra0);
        *(float4*)&a[arow * 28 + ak0 + 4] = cvt4(ra1);
        float* bb = BsBuf[0];
        *(float4*)&bb[br0 * 136 + bc0] = cvt4(rb0);
        *(float4*)&bb[br1 * 136 + bc1] = cvt4(rb1);
    }
    __syncthreads();

    for (int s = 0; s < nst; ++s) {
        const int p = s & 1;
        // prefetch next stage into regs (overlaps mma)
        if (s + 1 < nst) {
            const int k0 = (s + 1) * 16;
            ra0 = *(const float4*)(Ap + k0);
            ra1 = *(const float4*)(Ap + k0 + 4);
            rb0 = *(const float4*)(Bp0 + (size_t)k0 * N);
            rb1 = *(const float4*)(Bp1 + (size_t)k0 * N);
        }

        const float* a  = AsBuf[p];
        const float* bb = BsBuf[p];
#pragma unroll
        for (int ks = 0; ks < 2; ++ks) {
            const int k0 = ks * 8;
            float af[4][4];
#pragma unroll
            for (int mf = 0; mf < 4; ++mf) {
                const int r0 = (wm * 64 + mf * 16 + g) * 28 + k0 + q;
                af[mf][0] = a[r0];
                af[mf][1] = a[r0 + 8 * 28];
                af[mf][2] = a[r0 + 4];
                af[mf][3] = a[r0 + 8 * 28 + 4];
            }
#pragma unroll
            for (int nf = 0; nf < 4; ++nf) {
                float bf[2];
                const int c = wn * 32 + nf * 8 + g;
                bf[0] = bb[(k0 + q) * 136 + c];
                bf[1] = bb[(k0 + q + 4) * 136 + c];
#pragma unroll
                for (int mf = 0; mf < 4; ++mf)
                    mma_tf32(acc[mf][nf], af[mf], bf);
            }
        }

        if (s + 1 < nst) {
            float* an = AsBuf[1 - p];
            *(float4*)&an[arow * 28 + ak0]     = cvt4(ra0);
            *(float4*)&an[arow * 28 + ak0 + 4] = cvt4(ra1);
            float* bn2 = BsBuf[1 - p];
            *(float4*)&bn2[br0 * 136 + bc0] = cvt4(rb0);
            *(float4*)&bn2[br1 * 136 + bc1] = cvt4(rb1);
        }
        __syncthreads();
    }

    // epilogue: + bias, float2 stores
#pragma unroll
    for (int mf = 0; mf < 4; ++mf) {
        const int row = bm + wm * 64 + mf * 16 + g;
#pragma unroll
        for (int nf = 0; nf < 4; ++nf) {
            const int col = bn + wn * 32 + nf * 8 + 2 * q;
            float2 bv = *(const float2*)(bias + col);
            float2 v0 = { acc[mf][nf][0] + bv.x, acc[mf][nf][1] + bv.y };
            *(float2*)(C + (size_t)row * N + col) = v0;
            float2 v1 = { acc[mf][nf][2] + bv.x, acc[mf][nf][3] + bv.y };
            *(float2*)(C + (size_t)(row + 8) * N + col) = v1;
        }
    }
}

// ===========================================================================
// Fused causal attention (flash style) on mma.sync tf32.
// Block = (qt, h, b): 64 q-rows, 4 warps x 16 rows; KV tiles of 64.
// Ks/Vs [64][72]; Ps per-warp [16][72]. Q frags persistent (scale folded).
// ===========================================================================
#define KS_OFF 0
#define VS_OFF 4608              // 64*72
#define PS_OFF 9216              // 2*64*72
#define ATTN_SMEM ((9216 + 4*16*72)*4)   // 55296 bytes

__global__ void __launch_bounds__(128)
attn_tc(const float* __restrict__ qkv, float* __restrict__ ctx) {
    const int qt = blockIdx.x;
    const int h  = blockIdx.y;
    const int b  = blockIdx.z;

    const int tid = threadIdx.x;
    const int lane = tid & 31;
    const int wid = tid >> 5;
    const int g = lane >> 2;
    const int q = lane & 3;

    extern __shared__ float sms[];
    float* Ks = sms + KS_OFF;
    float* Vs = sms + VS_OFF;
    float* Pw = sms + PS_OFF + wid * (16 * 72);

    // ---- stage Q (scaled) into Ks, then pull persistent A-fragments ----
    {
        const float* qb = qkv + (size_t)(b * SEQ + qt * 64) * QKV_N + h * HSZ;
#pragma unroll
        for (int r = 0; r < 8; ++r) {
            const int f = tid + 128 * r;
            const int row = f >> 4, c4 = (f & 15) * 4;
            float4 v = *(const float4*)(qb + (size_t)row * QKV_N + c4);
            v.x *= 0.125f; v.y *= 0.125f; v.z *= 0.125f; v.w *= 0.125f;
            *(float4*)&Ks[row * 72 + c4] = cvt4(v);
        }
    }
    __syncthreads();
    float qa[8][4];
#pragma unroll
    for (int ks = 0; ks < 8; ++ks) {
        const int r0 = (wid * 16 + g) * 72 + ks * 8 + q;
        qa[ks][0] = Ks[r0];
        qa[ks][1] = Ks[r0 + 8 * 72];
        qa[ks][2] = Ks[r0 + 4];
        qa[ks][3] = Ks[r0 + 8 * 72 + 4];
    }

    float o[8][4];
#pragma unroll
    for (int nf = 0; nf < 8; ++nf)
#pragma unroll
        for (int e = 0; e < 4; ++e) o[nf][e] = 0.f;
    float m0 = -1e30f, m1 = -1e30f, l0 = 0.f, l1 = 0.f;

    for (int kt = 0; kt <= qt; ++kt) {
        __syncthreads();   // prior reads of Ks/Vs done (also covers qa loads)
        // ---- stage K, V ----
        {
            const float* kb = qkv + (size_t)(b * SEQ + kt * 64) * QKV_N + HID + h * HSZ;
#pragma unroll
            for (int r = 0; r < 8; ++r) {
                const int f = tid + 128 * r;
                const int row = f >> 4, c4 = (f & 15) * 4;
                float4 kv = *(const float4*)(kb + (size_t)row * QKV_N + c4);
                *(float4*)&Ks[row * 72 + c4] = cvt4(kv);
                float4 vv = *(const float4*)(kb + HID + (size_t)row * QKV_N + c4);
                *(float4*)&Vs[row * 72 + c4] = cvt4(vv);
            }
        }
        __syncthreads();

        const int nlim = (kt == qt) ? (2 * wid + 2) : 8;

        // ---- S = Q @ K^T ----
        float s[8][4];
        for (int nf = 0; nf < nlim; ++nf) {
            s[nf][0] = 0.f; s[nf][1] = 0.f; s[nf][2] = 0.f; s[nf][3] = 0.f;
            const int nrow = (nf * 8 + g) * 72;
#pragma unroll
            for (int ks = 0; ks < 8; ++ks) {
                float bf[2];
                bf[0] = Ks[nrow + ks * 8 + q];
                bf[1] = Ks[nrow + ks * 8 + q + 4];
                mma_tf32(s[nf], qa[ks], bf);
            }
        }

        // ---- causal mask on the diagonal tile ----
        if (kt == qt) {
            const int q0 = wid * 16 + g;
            for (int nf = 0; nf < nlim; ++nf) {
                const int key = nf * 8 + 2 * q;
                if (key     > q0)     s[nf][0] = -1e30f;
                if (key + 1 > q0)     s[nf][1] = -1e30f;
                if (key     > q0 + 8) s[nf][2] = -1e30f;
                if (key + 1 > q0 + 8) s[nf][3] = -1e30f;
            }
        }

        // ---- online softmax (rows g and g+8; reduce across lane-quads) ----
        float mx0 = -1e30f, mx1 = -1e30f;
        for (int nf = 0; nf < nlim; ++nf) {
            mx0 = fmaxf(mx0, fmaxf(s[nf][0], s[nf][1]));
            mx1 = fmaxf(mx1, fmaxf(s[nf][2], s[nf][3]));
        }
        mx0 = fmaxf(mx0, __shfl_xor_sync(0xffffffffu, mx0, 1));
        mx0 = fmaxf(mx0, __shfl_xor_sync(0xffffffffu, mx0, 2));
        mx1 = fmaxf(mx1, __shfl_xor_sync(0xffffffffu, mx1, 1));
        mx1 = fmaxf(mx1, __shfl_xor_sync(0xffffffffu, mx1, 2));

        const float mn0 = fmaxf(m0, mx0), mn1 = fmaxf(m1, mx1);
        const float a0 = __expf(m0 - mn0), a1 = __expf(m1 - mn1);
        m0 = mn0; m1 = mn1;

        float sum0 = 0.f, sum1 = 0.f;
        for (int nf = 0; nf < nlim; ++nf) {
            s[nf][0] = __expf(s[nf][0] - mn0);
            s[nf][1] = __expf(s[nf][1] - mn0);
            s[nf][2] = __expf(s[nf][2] - mn1);
            s[nf][3] = __expf(s[nf][3] - mn1);
            sum0 += s[nf][0] + s[nf][1];
            sum1 += s[nf][2] + s[nf][3];
        }
        sum0 += __shfl_xor_sync(0xffffffffu, sum0, 1);
        sum0 += __shfl_xor_sync(0xffffffffu, sum0, 2);
        sum1 += __shfl_xor_sync(0xffffffffu, sum1, 1);
        sum1 += __shfl_xor_sync(0xffffffffu, sum1, 2);
        l0 = l0 * a0 + sum0;
        l1 = l1 * a1 + sum1;
#pragma unroll
        for (int nf = 0; nf < 8; ++nf) {
            o[nf][0] *= a0; o[nf][1] *= a0;
            o[nf][2] *= a1; o[nf][3] *= a1;
        }

        // ---- P -> per-warp SMEM (tf32) ----
        for (int nf = 0; nf < nlim; ++nf) {
            const int c = nf * 8 + 2 * q;
            Pw[g * 72 + c]           = to_tf32(s[nf][0]);
            Pw[g * 72 + c + 1]       = to_tf32(s[nf][1]);
            Pw[(g + 8) * 72 + c]     = to_tf32(s[nf][2]);
            Pw[(g + 8) * 72 + c + 1] = to_tf32(s[nf][3]);
        }
        __syncwarp();

        // ---- O += P @ V ----
        for (int ks = 0; ks < nlim; ++ks) {
            float pf[4];
            const int pr = g * 72 + ks * 8 + q;
            pf[0] = Pw[pr];
            pf[1] = Pw[pr + 8 * 72];
            pf[2] = Pw[pr + 4];
            pf[3] = Pw[pr + 8 * 72 + 4];
#pragma unroll
            for (int nf = 0; nf < 8; ++nf) {
                float bf[2];
                bf[0] = Vs[(ks * 8 + q) * 72 + nf * 8 + g];
                bf[1] = Vs[(ks * 8 + q + 4) * 72 + nf * 8 + g];
                mma_tf32(o[nf], pf, bf);
            }
        }
        __syncwarp();
    }

    // ---- normalize + write ctx ----
    const float inv0 = 1.0f / l0, inv1 = 1.0f / l1;
    float* ob = ctx + (size_t)(b * SEQ + qt * 64 + wid * 16 + g) * HID + h * HSZ;
#pragma unroll
    for (int nf = 0; nf < 8; ++nf) {
        const int c = nf * 8 + 2 * q;
        float2 v0 = { o[nf][0] * inv0, o[nf][1] * inv0 };
        *(float2*)(ob + c) = v0;
        float2 v1 = { o[nf][2] * inv1, o[nf][3] * inv1 };
        *(float2*)(ob + (size_t)8 * HID + c) = v1;
    }
}

// ===========================================================================
extern "C" void kernel_launch(void* const* d_in, const int* in_sizes, int n_in,
                              void* d_out, int out_size) {
    const float* hs = (const float*)d_in[0];
    const float* w1 = (const float*)d_in[1];
    const float* b1 = (const float*)d_in[2];
    const float* w2 = (const float*)d_in[3];
    const float* b2 = (const float*)d_in[4];
    float* out = (float*)d_out;

    float* qkv;  cudaGetSymbolAddress((void**)&qkv, g_qkv);
    float* ctx;  cudaGetSymbolAddress((void**)&ctx, g_ctx);

    cudaFuncSetAttribute(gemm_tc,
                         cudaFuncAttributeMaxDynamicSharedMemorySize, GEMM_SMEM);
    cudaFuncSetAttribute(attn_tc,
                         cudaFuncAttributeMaxDynamicSharedMemorySize, ATTN_SMEM);

    // 1) QKV projection: [4096,768] @ [768,2304] + bias
    gemm_tc<<<dim3(QKV_N / 128, M_TOK / 128), 256, GEMM_SMEM>>>(
        hs, w1, b1, qkv, M_TOK, QKV_N, HID);

    // 2) fused causal attention (tensor core)
    attn_tc<<<dim3(SEQ / 64, NHEAD, BATCH), 128, ATTN_SMEM>>>(qkv, ctx);

    // 3) output projection: [4096,768] @ [768,768] + bias
    gemm_tc<<<dim3(HID / 128, M_TOK / 128), 256, GEMM_SMEM>>>(
        ctx, w2, b2, out, M_TOK, HID, HID);
}

// round 4
// speedup vs baseline: 2.2774x; 1.0035x over previous
#include <cuda_runtime.h>
#include <cstdint>

// Problem constants (fixed by the reference)
#define BATCH 2
#define SEQ   2048
#define NHEAD 12
#define HSZ   64
#define HID   768
#define M_TOK (BATCH*SEQ)   // 4096
#define QKV_N (3*HID)       // 2304

// Scratch (allocation-free rule: __device__ globals)
__device__ float g_qkv[M_TOK * QKV_N];
__device__ float g_ctx[M_TOK * HID];

// ===========================================================================
// helpers: tf32 convert (round-to-nearest!) + mma.sync m16n8k8 tf32
// ===========================================================================
__device__ __forceinline__ float to_tf32(float x) {
    uint32_t u;
    asm("cvt.rna.tf32.f32 %0, %1;" : "=r"(u) : "f"(x));
    return __uint_as_float(u);
}
__device__ __forceinline__ float4 cvt4(float4 v) {
    float4 r;
    r.x = to_tf32(v.x); r.y = to_tf32(v.y);
    r.z = to_tf32(v.z); r.w = to_tf32(v.w);
    return r;
}
__device__ __forceinline__ void mma_tf32(float* d, const float* a, const float* b) {
    asm volatile(
        "mma.sync.aligned.m16n8k8.row.col.f32.tf32.tf32.f32 "
        "{%0,%1,%2,%3}, {%4,%5,%6,%7}, {%8,%9}, {%0,%1,%2,%3};"
        : "+f"(d[0]), "+f"(d[1]), "+f"(d[2]), "+f"(d[3])
        : "r"(__float_as_uint(a[0])), "r"(__float_as_uint(a[1])),
          "r"(__float_as_uint(a[2])), "r"(__float_as_uint(a[3])),
          "r"(__float_as_uint(b[0])), "r"(__float_as_uint(b[1])));
}

// ===========================================================================
// GEMM (tensor core, tf32): C[M,N] = A[M,K] @ B[K,N] + bias[N]
// 128x128 tile, BK=16, 256 threads (8 warps as 2x4), warp tile 64x32.
// As[m][28] (pad 28: bank = (28g+q)%32 distinct), Bs[k][136] (bank 8q+g).
// ===========================================================================
#define AS_STRIDE 3584   // 128*28
#define BS_STRIDE 2176   // 16*136
#define GEMM_SMEM ((2*AS_STRIDE + 2*BS_STRIDE)*4)

__global__ void __launch_bounds__(256, 2)
gemm_tc(const float* __restrict__ A, const float* __restrict__ B,
        const float* __restrict__ bias, float* __restrict__ C,
        int M, int N, int K) {
    extern __shared__ float sm[];
    float* AsBuf[2] = { sm, sm + AS_STRIDE };
    float* BsBuf[2] = { sm + 2 * AS_STRIDE, sm + 2 * AS_STRIDE + BS_STRIDE };

    const int tid = threadIdx.x;
    const int lane = tid & 31;
    const int wid = tid >> 5;
    const int g = lane >> 2;     // groupID
    const int q = lane & 3;      // threadID_in_group
    const int wm = wid >> 2;     // 0..1  (64 rows)
    const int wn = wid & 3;      // 0..3  (32 cols)
    const int bm = blockIdx.y * 128;
    const int bn = blockIdx.x * 128;

    // ---- staging maps ----
    const int arow = tid >> 1;
    const int ak0  = (tid & 1) * 8;
    const float* Ap = A + (size_t)(bm + arow) * K + ak0;

    const int br0 = tid >> 5,        bc0 = (tid & 31) * 4;
    const int br1 = (tid + 256) >> 5, bc1 = (tid & 31) * 4;
    const float* Bp0 = B + (size_t)br0 * N + bn + bc0;
    const float* Bp1 = B + (size_t)br1 * N + bn + bc1;

    float acc[4][4][4];
#pragma unroll
    for (int mf = 0; mf < 4; ++mf)
#pragma unroll
        for (int nf = 0; nf < 4; ++nf)
#pragma unroll
            for (int e = 0; e < 4; ++e) acc[mf][nf][e] = 0.f;

    const int nst = K / 16;   // 48

    // prologue: load stage 0
    float4 ra0 = *(const float4*)(Ap);
    float4 ra1 = *(const float4*)(Ap + 4);
    float4 rb0 = *(const float4*)(Bp0);
    float4 rb1 = *(const float4*)(Bp1);
    {
        float* a = AsBuf[0];
        *(float4*)&a[arow * 28 + ak0]     = cvt4(ra0);
        *(float4*)&a[arow * 28 + ak0 + 4] = cvt4(ra1);
        float* bb = BsBuf[0];
        *(float4*)&bb[br0 * 136 + bc0] = cvt4(rb0);
        *(float4*)&bb[br1 * 136 + bc1] = cvt4(rb1);
    }
    __syncthreads();

    for (int s = 0; s < nst; ++s) {
        const int p = s & 1;
        // prefetch next stage into regs (overlaps mma)
        if (s + 1 < nst) {
            const int k0 = (s + 1) * 16;
            ra0 = *(const float4*)(Ap + k0);
            ra1 = *(const float4*)(Ap + k0 + 4);
            rb0 = *(const float4*)(Bp0 + (size_t)k0 * N);
            rb1 = *(const float4*)(Bp1 + (size_t)k0 * N);
        }

        const float* a  = AsBuf[p];
        const float* bb = BsBuf[p];
#pragma unroll
        for (int ks = 0; ks < 2; ++ks) {
            const int k0 = ks * 8;
            float af[4][4];
#pragma unroll
            for (int mf = 0; mf < 4; ++mf) {
                const int r0 = (wm * 64 + mf * 16 + g) * 28 + k0 + q;
                af[mf][0] = a[r0];
                af[mf][1] = a[r0 + 8 * 28];
                af[mf][2] = a[r0 + 4];
                af[mf][3] = a[r0 + 8 * 28 + 4];
            }
#pragma unroll
            for (int nf = 0; nf < 4; ++nf) {
                float bf[2];
                const int c = wn * 32 + nf * 8 + g;
                bf[0] = bb[(k0 + q) * 136 + c];
                bf[1] = bb[(k0 + q + 4) * 136 + c];
#pragma unroll
                for (int mf = 0; mf < 4; ++mf)
                    mma_tf32(acc[mf][nf], af[mf], bf);
            }
        }

        if (s + 1 < nst) {
            float* an = AsBuf[1 - p];
            *(float4*)&an[arow * 28 + ak0]     = cvt4(ra0);
            *(float4*)&an[arow * 28 + ak0 + 4] = cvt4(ra1);
            float* bn2 = BsBuf[1 - p];
            *(float4*)&bn2[br0 * 136 + bc0] = cvt4(rb0);
            *(float4*)&bn2[br1 * 136 + bc1] = cvt4(rb1);
        }
        __syncthreads();
    }

    // epilogue: + bias, float2 stores
#pragma unroll
    for (int mf = 0; mf < 4; ++mf) {
        const int row = bm + wm * 64 + mf * 16 + g;
#pragma unroll
        for (int nf = 0; nf < 4; ++nf) {
            const int col = bn + wn * 32 + nf * 8 + 2 * q;
            float2 bv = *(const float2*)(bias + col);
            float2 v0 = { acc[mf][nf][0] + bv.x, acc[mf][nf][1] + bv.y };
            *(float2*)(C + (size_t)row * N + col) = v0;
            float2 v1 = { acc[mf][nf][2] + bv.x, acc[mf][nf][3] + bv.y };
            *(float2*)(C + (size_t)(row + 8) * N + col) = v1;
        }
    }
}

// ===========================================================================
// Fused causal attention (flash style) on mma.sync tf32.
// Block = (qt, h, b): 64 q-rows, 4 warps x 16 rows; KV tiles of 64.
// Ks/Vs [64][72]; Ps per-warp [16][72]. Q frags persistent (scale folded).
// ===========================================================================
#define KS_OFF 0
#define VS_OFF 4608              // 64*72
#define PS_OFF 9216              // 2*64*72
#define ATTN_SMEM ((9216 + 4*16*72)*4)   // 55296 bytes

__global__ void __launch_bounds__(128)
attn_tc(const float* __restrict__ qkv, float* __restrict__ ctx) {
    const int qt = blockIdx.x;
    const int h  = blockIdx.y;
    const int b  = blockIdx.z;

    const int tid = threadIdx.x;
    const int lane = tid & 31;
    const int wid = tid >> 5;
    const int g = lane >> 2;
    const int q = lane & 3;

    extern __shared__ float sms[];
    float* Ks = sms + KS_OFF;
    float* Vs = sms + VS_OFF;
    float* Pw = sms + PS_OFF + wid * (16 * 72);

    // ---- stage Q (scaled) into Ks, then pull persistent A-fragments ----
    {
        const float* qb = qkv + (size_t)(b * SEQ + qt * 64) * QKV_N + h * HSZ;
#pragma unroll
        for (int r = 0; r < 8; ++r) {
            const int f = tid + 128 * r;
            const int row = f >> 4, c4 = (f & 15) * 4;
            float4 v = *(const float4*)(qb + (size_t)row * QKV_N + c4);
            v.x *= 0.125f; v.y *= 0.125f; v.z *= 0.125f; v.w *= 0.125f;
            *(float4*)&Ks[row * 72 + c4] = cvt4(v);
        }
    }
    __syncthreads();
    float qa[8][4];
#pragma unroll
    for (int ks = 0; ks < 8; ++ks) {
        const int r0 = (wid * 16 + g) * 72 + ks * 8 + q;
        qa[ks][0] = Ks[r0];
        qa[ks][1] = Ks[r0 + 8 * 72];
        qa[ks][2] = Ks[r0 + 4];
        qa[ks][3] = Ks[r0 + 8 * 72 + 4];
    }

    float o[8][4];
#pragma unroll
    for (int nf = 0; nf < 8; ++nf)
#pragma unroll
        for (int e = 0; e < 4; ++e) o[nf][e] = 0.f;
    float m0 = -1e30f, m1 = -1e30f, l0 = 0.f, l1 = 0.f;

    for (int kt = 0; kt <= qt; ++kt) {
        __syncthreads();   // prior reads of Ks/Vs done (also covers qa loads)
        // ---- stage K, V ----
        {
            const float* kb = qkv + (size_t)(b * SEQ + kt * 64) * QKV_N + HID + h * HSZ;
#pragma unroll
            for (int r = 0; r < 8; ++r) {
                const int f = tid + 128 * r;
                const int row = f >> 4, c4 = (f & 15) * 4;
                float4 kv = *(const float4*)(kb + (size_t)row * QKV_N + c4);
                *(float4*)&Ks[row * 72 + c4] = cvt4(kv);
                float4 vv = *(const float4*)(kb + HID + (size_t)row * QKV_N + c4);
                *(float4*)&Vs[row * 72 + c4] = cvt4(vv);
            }
        }
        __syncthreads();

        const int nlim = (kt == qt) ? (2 * wid + 2) : 8;

        // ---- S = Q @ K^T ----
        float s[8][4];
        for (int nf = 0; nf < nlim; ++nf) {
            s[nf][0] = 0.f; s[nf][1] = 0.f; s[nf][2] = 0.f; s[nf][3] = 0.f;
            const int nrow = (nf * 8 + g) * 72;
#pragma unroll
            for (int ks = 0; ks < 8; ++ks) {
                float bf[2];
                bf[0] = Ks[nrow + ks * 8 + q];
                bf[1] = Ks[nrow + ks * 8 + q + 4];
                mma_tf32(s[nf], qa[ks], bf);
            }
        }

        // ---- causal mask on the diagonal tile ----
        if (kt == qt) {
            const int q0 = wid * 16 + g;
            for (int nf = 0; nf < nlim; ++nf) {
                const int key = nf * 8 + 2 * q;
                if (key     > q0)     s[nf][0] = -1e30f;
                if (key + 1 > q0)     s[nf][1] = -1e30f;
                if (key     > q0 + 8) s[nf][2] = -1e30f;
                if (key + 1 > q0 + 8) s[nf][3] = -1e30f;
            }
        }

        // ---- online softmax (rows g and g+8; reduce across lane-quads) ----
        float mx0 = -1e30f, mx1 = -1e30f;
        for (int nf = 0; nf < nlim; ++nf) {
            mx0 = fmaxf(mx0, fmaxf(s[nf][0], s[nf][1]));
            mx1 = fmaxf(mx1, fmaxf(s[nf][2], s[nf][3]));
        }
        mx0 = fmaxf(mx0, __shfl_xor_sync(0xffffffffu, mx0, 1));
        mx0 = fmaxf(mx0, __shfl_xor_sync(0xffffffffu, mx0, 2));
        mx1 = fmaxf(mx1, __shfl_xor_sync(0xffffffffu, mx1, 1));
        mx1 = fmaxf(mx1, __shfl_xor_sync(0xffffffffu, mx1, 2));

        const float mn0 = fmaxf(m0, mx0), mn1 = fmaxf(m1, mx1);
        const float a0 = __expf(m0 - mn0), a1 = __expf(m1 - mn1);
        m0 = mn0; m1 = mn1;

        float sum0 = 0.f, sum1 = 0.f;
        for (int nf = 0; nf < nlim; ++nf) {
            s[nf][0] = __expf(s[nf][0] - mn0);
            s[nf][1] = __expf(s[nf][1] - mn0);
            s[nf][2] = __expf(s[nf][2] - mn1);
            s[nf][3] = __expf(s[nf][3] - mn1);
            sum0 += s[nf][0] + s[nf][1];
            sum1 += s[nf][2] + s[nf][3];
        }
        sum0 += __shfl_xor_sync(0xffffffffu, sum0, 1);
        sum0 += __shfl_xor_sync(0xffffffffu, sum0, 2);
        sum1 += __shfl_xor_sync(0xffffffffu, sum1, 1);
        sum1 += __shfl_xor_sync(0xffffffffu, sum1, 2);
        l0 = l0 * a0 + sum0;
        l1 = l1 * a1 + sum1;
#pragma unroll
        for (int nf = 0; nf < 8; ++nf) {
            o[nf][0] *= a0; o[nf][1] *= a0;
            o[nf][2] *= a1; o[nf][3] *= a1;
        }

        // ---- P -> per-warp SMEM (tf32) ----
        for (int nf = 0; nf < nlim; ++nf) {
            const int c = nf * 8 + 2 * q;
            Pw[g * 72 + c]           = to_tf32(s[nf][0]);
            Pw[g * 72 + c + 1]       = to_tf32(s[nf][1]);
            Pw[(g + 8) * 72 + c]     = to_tf32(s[nf][2]);
            Pw[(g + 8) * 72 + c + 1] = to_tf32(s[nf][3]);
        }
        __syncwarp();

        // ---- O += P @ V ----
        for (int ks = 0; ks < nlim; ++ks) {
            float pf[4];
            const int pr = g * 72 + ks * 8 + q;
            pf[0] = Pw[pr];
            pf[1] = Pw[pr + 8 * 72];
            pf[2] = Pw[pr + 4];
            pf[3] = Pw[pr + 8 * 72 + 4];
#pragma unroll
            for (int nf = 0; nf < 8; ++nf) {
                float bf[2];
                bf[0] = Vs[(ks * 8 + q) * 72 + nf * 8 + g];
                bf[1] = Vs[(ks * 8 + q + 4) * 72 + nf * 8 + g];
                mma_tf32(o[nf], pf, bf);
            }
        }
        __syncwarp();
    }

    // ---- normalize + write ctx ----
    const float inv0 = 1.0f / l0, inv1 = 1.0f / l1;
    float* ob = ctx + (size_t)(b * SEQ + qt * 64 + wid * 16 + g) * HID + h * HSZ;
#pragma unroll
    for (int nf = 0; nf < 8; ++nf) {
        const int c = nf * 8 + 2 * q;
        float2 v0 = { o[nf][0] * inv0, o[nf][1] * inv0 };
        *(float2*)(ob + c) = v0;
        float2 v1 = { o[nf][2] * inv1, o[nf][3] * inv1 };
        *(float2*)(ob + (size_t)8 * HID + c) = v1;
    }
}

// ===========================================================================
extern "C" void kernel_launch(void* const* d_in, const int* in_sizes, int n_in,
                              void* d_out, int out_size) {
    const float* hs = (const float*)d_in[0];
    const float* w1 = (const float*)d_in[1];
    const float* b1 = (const float*)d_in[2];
    const float* w2 = (const float*)d_in[3];
    const float* b2 = (const float*)d_in[4];
    float* out = (float*)d_out;

    float* qkv;  cudaGetSymbolAddress((void**)&qkv, g_qkv);
    float* ctx;  cudaGetSymbolAddress((void**)&ctx, g_ctx);

    cudaFuncSetAttribute(gemm_tc,
                         cudaFuncAttributeMaxDynamicSharedMemorySize, GEMM_SMEM);
    cudaFuncSetAttribute(attn_tc,
                         cudaFuncAttributeMaxDynamicSharedMemorySize, ATTN_SMEM);

    // 1) QKV projection: [4096,768] @ [768,2304] + bias
    gemm_tc<<<dim3(QKV_N / 128, M_TOK / 128), 256, GEMM_SMEM>>>(
        hs, w1, b1, qkv, M_TOK, QKV_N, HID);

    // 2) fused causal attention (tensor core)
    attn_tc<<<dim3(SEQ / 64, NHEAD, BATCH), 128, ATTN_SMEM>>>(qkv, ctx);

    // 3) output projection: [4096,768] @ [768,768] + bias
    gemm_tc<<<dim3(HID / 128, M_TOK / 128), 256, GEMM_SMEM>>>(
        ctx, w2, b2, out, M_TOK, HID, HID);
}